// round 2
// baseline (speedup 1.0000x reference)
#include <cuda_runtime.h>

#define NN   100000
#define NE   1600000
#define KIN  128
#define NOUT 256
#define CAP  96
#define MT   128                 // GEMM M tile
#define NPAD 100096              // NN padded to multiple of MT
#define KC   16                  // GEMM K chunk
#define APITCH 132               // sAT row pitch (floats)

// Scratch (device globals: allocation-free per harness rules)
__device__ int   g_cnt[NN];
__device__ int   g_slot[(size_t)NN * CAP];
__device__ float g_agg[(size_t)NPAD * KIN];   // zero-init; pad rows stay 0

// ---------------- packed f32x2 helpers ----------------
__device__ __forceinline__ unsigned long long pk(float lo, float hi) {
    unsigned long long r;
    asm("mov.b64 %0, {%1, %2};" : "=l"(r) : "f"(lo), "f"(hi));
    return r;
}
__device__ __forceinline__ void fma2(unsigned long long& c, unsigned long long a,
                                     unsigned long long b) {
    asm("fma.rn.f32x2 %0, %1, %2, %0;" : "+l"(c) : "l"(a), "l"(b));
}
__device__ __forceinline__ float2 upk(unsigned long long v) {
    float2 f;
    asm("mov.b64 {%0, %1}, %2;" : "=f"(f.x), "=f"(f.y) : "l"(v));
    return f;
}

// ---------------- K1: zero degree counters ----------------
__global__ void k_zero_cnt() {
    int i = blockIdx.x * blockDim.x + threadIdx.x;
    if (i < NN) g_cnt[i] = 0;
}

// ---------------- K2: bucket fill ----------------
__global__ void k_fill(const int* __restrict__ src, const int* __restrict__ dst) {
    int e = blockIdx.x * blockDim.x + threadIdx.x;
    if (e >= NE) return;
    int d = dst[e];
    int p = atomicAdd(&g_cnt[d], 1);
    if (p < CAP) g_slot[(size_t)d * CAP + p] = src[e];
}

// ---------------- K3: gather aggregation (warp per node) ----------------
__global__ void __launch_bounds__(256) k_agg(const float* __restrict__ feat) {
    int w    = (blockIdx.x * blockDim.x + threadIdx.x) >> 5;
    int lane = threadIdx.x & 31;
    if (w >= NN) return;

    int deg = g_cnt[w];
    deg = deg < CAP ? deg : CAP;

    const float4* f4 = (const float4*)feat;
    float4 acc = f4[(size_t)w * 32 + lane];          // self loop

    const int* sl = g_slot + (size_t)w * CAP;
    int i = 0;
    for (; i + 4 <= deg; i += 4) {
        int s0 = sl[i], s1 = sl[i + 1], s2 = sl[i + 2], s3 = sl[i + 3];
        float4 v0 = f4[(size_t)s0 * 32 + lane];
        float4 v1 = f4[(size_t)s1 * 32 + lane];
        float4 v2 = f4[(size_t)s2 * 32 + lane];
        float4 v3 = f4[(size_t)s3 * 32 + lane];
        acc.x += (v0.x + v1.x) + (v2.x + v3.x);
        acc.y += (v0.y + v1.y) + (v2.y + v3.y);
        acc.z += (v0.z + v1.z) + (v2.z + v3.z);
        acc.w += (v0.w + v1.w) + (v2.w + v3.w);
    }
    for (; i < deg; i++) {
        float4 v = f4[(size_t)sl[i] * 32 + lane];
        acc.x += v.x; acc.y += v.y; acc.z += v.z; acc.w += v.w;
    }
    ((float4*)g_agg)[(size_t)w * 32 + lane] = acc;
}

// ---------------- K4: fp32 GEMM, K-chunked, register-prefetch pipeline ----
// 256 threads; block tile 128x256; thread tile 8 rows x 16 cols.
// smem: sW [KC][NOUT] 16KB + sAT [KC][APITCH] k-major 8.25KB  (static, <48KB)
__global__ void __launch_bounds__(256, 1) k_gemm(const float* __restrict__ W,
                                                 const float* __restrict__ bias,
                                                 float* __restrict__ out) {
    __shared__ float sW[KC * NOUT];        // [k][n]
    __shared__ float sAT[KC * APITCH];     // [k][m] (k-major, padded)

    int tid = threadIdx.x;
    int tx  = tid & 15;                    // N: cols tx*16 .. +15
    int ty  = tid >> 4;                    // M: rows ty*8 .. +7
    int m0  = blockIdx.x * MT;

    const float4* W4 = (const float4*)W;                           // 128x64 f4
    const float4* A4 = (const float4*)g_agg + (size_t)m0 * (KIN/4);// tile base

    // prefetch registers
    float4 wreg[4];   // 16 W floats / thread / chunk
    float4 areg[2];   // 8  A floats / thread / chunk

    // ---- prologue: LDG chunk 0 ----
    #pragma unroll
    for (int i = 0; i < 4; i++) wreg[i] = W4[tid + i * 256];       // chunk 0
    {
        int idx0 = tid, idx1 = tid + 256;
        areg[0] = A4[(idx0 >> 2) * 32 + (idx0 & 3)];
        areg[1] = A4[(idx1 >> 2) * 32 + (idx1 & 3)];
    }

    unsigned long long c[8][8];
    #pragma unroll
    for (int i = 0; i < 8; i++)
        #pragma unroll
        for (int j = 0; j < 8; j++) c[i][j] = 0ULL;

    const float4* sW4 = (const float4*)sW;

    for (int ch = 0; ch < KIN / KC; ch++) {
        // ---- stage current chunk into smem ----
        #pragma unroll
        for (int i = 0; i < 4; i++)
            *(float4*)(sW + (tid + i * 256) * 4) = wreg[i];
        #pragma unroll
        for (int i = 0; i < 2; i++) {
            int idx = tid + i * 256;       // 0..511
            int m = idx >> 2, q = idx & 3; // q = k-quad within chunk
            float4 v = areg[i];
            sAT[(q * 4 + 0) * APITCH + m] = v.x;
            sAT[(q * 4 + 1) * APITCH + m] = v.y;
            sAT[(q * 4 + 2) * APITCH + m] = v.z;
            sAT[(q * 4 + 3) * APITCH + m] = v.w;
        }
        __syncthreads();

        // ---- prefetch next chunk (LDG overlaps compute below) ----
        if (ch < KIN / KC - 1) {
            int kb = (ch + 1) * KC;
            #pragma unroll
            for (int i = 0; i < 4; i++)
                wreg[i] = W4[kb * 64 + tid + i * 256];
            int idx0 = tid, idx1 = tid + 256;
            areg[0] = A4[(idx0 >> 2) * 32 + kb / 4 + (idx0 & 3)];
            areg[1] = A4[(idx1 >> 2) * 32 + kb / 4 + (idx1 & 3)];
        }

        // ---- compute chunk ----
        #pragma unroll
        for (int k = 0; k < KC; k++) {
            float4 b0 = sW4[k * 64 + tx * 4 + 0];
            float4 b1 = sW4[k * 64 + tx * 4 + 1];
            float4 b2 = sW4[k * 64 + tx * 4 + 2];
            float4 b3 = sW4[k * 64 + tx * 4 + 3];
            unsigned long long bb[8];
            bb[0] = pk(b0.x, b0.y); bb[1] = pk(b0.z, b0.w);
            bb[2] = pk(b1.x, b1.y); bb[3] = pk(b1.z, b1.w);
            bb[4] = pk(b2.x, b2.y); bb[5] = pk(b2.z, b2.w);
            bb[6] = pk(b3.x, b3.y); bb[7] = pk(b3.z, b3.w);

            // 8 contiguous A rows for this thread: two LDS.128
            float4 a01 = *(const float4*)(sAT + k * APITCH + ty * 8);
            float4 a23 = *(const float4*)(sAT + k * APITCH + ty * 8 + 4);
            float av[8] = {a01.x, a01.y, a01.z, a01.w,
                           a23.x, a23.y, a23.z, a23.w};
            #pragma unroll
            for (int i = 0; i < 8; i++) {
                unsigned long long aa = pk(av[i], av[i]);
                #pragma unroll
                for (int j = 0; j < 8; j++) fma2(c[i][j], aa, bb[j]);
            }
        }
        __syncthreads();
    }

    // ---- epilogue: bias add + store ----
    float4 bv[4];
    {
        const float4* b4 = (const float4*)bias;
        #pragma unroll
        for (int j = 0; j < 4; j++) bv[j] = b4[tx * 4 + j];
    }
    #pragma unroll
    for (int i = 0; i < 8; i++) {
        int row = m0 + ty * 8 + i;
        if (row < NN) {
            float4* o4 = (float4*)(out + (size_t)row * NOUT + tx * 16);
            #pragma unroll
            for (int j = 0; j < 4; j++) {
                float2 lo = upk(c[i][2 * j]);
                float2 hi = upk(c[i][2 * j + 1]);
                o4[j] = make_float4(lo.x + bv[j].x, lo.y + bv[j].y,
                                    hi.x + bv[j].z, hi.y + bv[j].w);
            }
        }
    }
}

extern "C" void kernel_launch(void* const* d_in, const int* in_sizes, int n_in,
                              void* d_out, int out_size) {
    const float* features = (const float*)d_in[0];
    const int*   src      = (const int*)d_in[1];
    const int*   dst      = (const int*)d_in[2];
    const float* W        = (const float*)d_in[3];
    const float* bias     = (const float*)d_in[4];
    float*       out      = (float*)d_out;

    k_zero_cnt<<<(NN + 255) / 256, 256>>>();
    k_fill<<<(NE + 255) / 256, 256>>>(src, dst);
    k_agg<<<NN / 8, 256>>>(features);
    k_gemm<<<NPAD / MT, 256>>>(W, bias, out);
}

// round 6
// speedup vs baseline: 2.1084x; 2.1084x over previous
#include <cuda_runtime.h>
#include <cuda_bf16.h>
#include <cstdint>

#define NN   100000
#define NE   1600000
#define KIN  128
#define NOUT 256
#define CAP  96
#define MT   128
#define NTB  128                  // GEMM N tile per CTA
#define NPAD 100096               // NN padded to multiple of MT
#define PITCH 40                  // smem row pitch in bf16 (80B) -> ldmatrix conflict-free

// ---------------- scratch (device globals; allocation-free) ----------------
__device__ int            g_cnt[NN];
__device__ int            g_slot[(size_t)NN * CAP];
__device__ __nv_bfloat16  g_Ahi[(size_t)NPAD * KIN];   // aggregated feats, hi
__device__ __nv_bfloat16  g_Alo[(size_t)NPAD * KIN];   // aggregated feats, lo
__device__ __nv_bfloat16  g_Bhi[NOUT * KIN];           // W^T [n][k], hi
__device__ __nv_bfloat16  g_Blo[NOUT * KIN];           // W^T [n][k], lo

// ---------------- helpers ----------------
__device__ __forceinline__ uint32_t smem_u32(const void* p) {
    uint32_t a;
    asm("{ .reg .u64 t; cvta.to.shared.u64 t, %1; cvt.u32.u64 %0, t; }"
        : "=r"(a) : "l"(p));
    return a;
}
__device__ __forceinline__ void split2(float x, __nv_bfloat16& hi, __nv_bfloat16& lo) {
    hi = __float2bfloat16(x);
    lo = __float2bfloat16(x - __bfloat162float(hi));
}

#define LDSM4(r0, r1, r2, r3, addr) \
    asm volatile("ldmatrix.sync.aligned.m8n8.x4.shared.b16 {%0,%1,%2,%3}, [%4];" \
                 : "=r"(r0), "=r"(r1), "=r"(r2), "=r"(r3) : "r"(addr))

#define MMA16816(c, a, b0, b1) \
    asm volatile("mma.sync.aligned.m16n8k16.row.col.f32.bf16.bf16.f32 " \
                 "{%0,%1,%2,%3}, {%4,%5,%6,%7}, {%8,%9}, {%0,%1,%2,%3};" \
                 : "+f"((c)[0]), "+f"((c)[1]), "+f"((c)[2]), "+f"((c)[3]) \
                 : "r"((a)[0]), "r"((a)[1]), "r"((a)[2]), "r"((a)[3]), \
                   "r"(b0), "r"(b1))

// ---------------- K1: zero counters ----------------
__global__ void k_zero_cnt() {
    int i = blockIdx.x * blockDim.x + threadIdx.x;
    if (i < NN) g_cnt[i] = 0;
}

// ---------------- K2: bucket fill ----------------
__global__ void k_fill(const int* __restrict__ src, const int* __restrict__ dst) {
    int e = blockIdx.x * blockDim.x + threadIdx.x;
    if (e >= NE) return;
    int d = dst[e];
    int p = atomicAdd(&g_cnt[d], 1);
    if (p < CAP) g_slot[(size_t)d * CAP + p] = src[e];
}

// ---------------- K3: W^T hi/lo bf16 ----------------
__global__ void k_prepW(const float* __restrict__ W) {
    int i = blockIdx.x * blockDim.x + threadIdx.x;   // 0 .. 32767
    if (i >= NOUT * KIN) return;
    int n = i >> 7, k = i & 127;
    float w = W[k * NOUT + n];
    __nv_bfloat16 hi, lo;
    split2(w, hi, lo);
    g_Bhi[i] = hi;
    g_Blo[i] = lo;
}

// ---------------- K4: gather aggregation (warp per node) + bf16 split ------
__global__ void __launch_bounds__(256) k_agg(const float* __restrict__ feat) {
    int w    = (blockIdx.x * blockDim.x + threadIdx.x) >> 5;
    int lane = threadIdx.x & 31;
    if (w >= NN) return;

    int deg = g_cnt[w];
    deg = deg < CAP ? deg : CAP;

    const float4* f4 = (const float4*)feat;
    float4 acc = f4[(size_t)w * 32 + lane];          // self loop

    const int* sl = g_slot + (size_t)w * CAP;
    int i = 0;
    for (; i + 4 <= deg; i += 4) {
        int s0 = sl[i], s1 = sl[i + 1], s2 = sl[i + 2], s3 = sl[i + 3];
        float4 v0 = f4[(size_t)s0 * 32 + lane];
        float4 v1 = f4[(size_t)s1 * 32 + lane];
        float4 v2 = f4[(size_t)s2 * 32 + lane];
        float4 v3 = f4[(size_t)s3 * 32 + lane];
        acc.x += (v0.x + v1.x) + (v2.x + v3.x);
        acc.y += (v0.y + v1.y) + (v2.y + v3.y);
        acc.z += (v0.z + v1.z) + (v2.z + v3.z);
        acc.w += (v0.w + v1.w) + (v2.w + v3.w);
    }
    for (; i < deg; i++) {
        float4 v = f4[(size_t)sl[i] * 32 + lane];
        acc.x += v.x; acc.y += v.y; acc.z += v.z; acc.w += v.w;
    }

    __nv_bfloat16 hx, lx, hy, ly, hz, lz, hw, lw;
    split2(acc.x, hx, lx); split2(acc.y, hy, ly);
    split2(acc.z, hz, lz); split2(acc.w, hw, lw);
    __nv_bfloat162* Ah = (__nv_bfloat162*)g_Ahi + (size_t)w * 64 + lane * 2;
    __nv_bfloat162* Al = (__nv_bfloat162*)g_Alo + (size_t)w * 64 + lane * 2;
    Ah[0] = __nv_bfloat162(hx, hy); Ah[1] = __nv_bfloat162(hz, hw);
    Al[0] = __nv_bfloat162(lx, ly); Al[1] = __nv_bfloat162(lz, lw);
}

// ---------------- K5: mma.sync bf16 GEMM, 3-pass compensated ---------------
// CTA tile 128x128; 8 warps as 4(M) x 2(N); warp tile 32x64.
// K in 4 chunks of 32 through smem (pitch 40 -> ldmatrix conflict-free).
__global__ void __launch_bounds__(256, 2) k_gemm_mma(const float* __restrict__ bias,
                                                     float* __restrict__ out) {
    __shared__ __align__(16) __nv_bfloat16 sAh[MT * PITCH];
    __shared__ __align__(16) __nv_bfloat16 sAl[MT * PITCH];
    __shared__ __align__(16) __nv_bfloat16 sBh[NTB * PITCH];
    __shared__ __align__(16) __nv_bfloat16 sBl[NTB * PITCH];
    __shared__ float sBias[NTB];

    int tid  = threadIdx.x;
    int wid  = tid >> 5;
    int l    = tid & 31;
    int mb   = blockIdx.x >> 1;
    int nb   = blockIdx.x & 1;
    int m0   = mb * MT;
    int n0   = nb * NTB;
    int wm   = (wid >> 1) * 32;            // warp M offset in tile
    int wn   = (wid & 1) * 64;             // warp N offset in tile

    if (tid < NTB) sBias[tid] = bias[n0 + tid];

    uint32_t uAh = smem_u32(sAh), uAl = smem_u32(sAl);
    uint32_t uBh = smem_u32(sBh), uBl = smem_u32(sBl);

    // ldmatrix lane base offsets (bytes)
    uint32_t laneA = (uint32_t)(wm + (l & 15)) * (PITCH * 2) + ((l >> 4) & 1) * 16;
    uint32_t laneB = (uint32_t)(wn + ((l >> 4) & 1) * 8 + (l & 7)) * (PITCH * 2)
                   + ((l >> 3) & 1) * 16;

    float acc[2][8][4];
    #pragma unroll
    for (int mi = 0; mi < 2; mi++)
        #pragma unroll
        for (int nj = 0; nj < 8; nj++)
            #pragma unroll
            for (int q = 0; q < 4; q++) acc[mi][nj][q] = 0.f;

    const uint2* pAh = (const uint2*)g_Ahi;   // 32 uint2 per 128-bf16 row
    const uint2* pAl = (const uint2*)g_Alo;
    const uint2* pBh = (const uint2*)g_Bhi;
    const uint2* pBl = (const uint2*)g_Blo;

    for (int kc = 0; kc < KIN / 32; kc++) {
        // ---- stage chunk: 128 rows x 32 k = 8 uint2/row per array ----
        #pragma unroll
        for (int i = 0; i < 4; i++) {
            int idx = tid + i * 256;           // 0..1023
            int r = idx >> 3, c = idx & 7;     // row 0..127, uint2 col 0..7
            uint32_t so = (uint32_t)r * (PITCH * 2) + c * 8;
            size_t ga = ((size_t)(m0 + r)) * 32 + kc * 8 + c;
            *(uint2*)((char*)sAh + so) = pAh[ga];
            *(uint2*)((char*)sAl + so) = pAl[ga];
            size_t gb = ((size_t)(n0 + r)) * 32 + kc * 8 + c;
            *(uint2*)((char*)sBh + so) = pBh[gb];
            *(uint2*)((char*)sBl + so) = pBl[gb];
        }
        __syncthreads();

        #pragma unroll
        for (int ks = 0; ks < 2; ks++) {
            uint32_t koff = ks * 32;            // 16 bf16 = 32 bytes
            uint32_t a[2][4], b[4][4];

            // pass 1: Ahi * Bhi
            LDSM4(a[0][0], a[0][1], a[0][2], a[0][3], uAh + laneA + koff);
            LDSM4(a[1][0], a[1][1], a[1][2], a[1][3], uAh + laneA + koff + 16 * PITCH * 2);
            #pragma unroll
            for (int g = 0; g < 4; g++)
                LDSM4(b[g][0], b[g][1], b[g][2], b[g][3],
                      uBh + laneB + koff + g * 16 * PITCH * 2);
            #pragma unroll
            for (int mi = 0; mi < 2; mi++)
                #pragma unroll
                for (int g = 0; g < 4; g++) {
                    MMA16816(acc[mi][g * 2 + 0], a[mi], b[g][0], b[g][1]);
                    MMA16816(acc[mi][g * 2 + 1], a[mi], b[g][2], b[g][3]);
                }

            // pass 2: Alo * Bhi  (reuse B frags)
            LDSM4(a[0][0], a[0][1], a[0][2], a[0][3], uAl + laneA + koff);
            LDSM4(a[1][0], a[1][1], a[1][2], a[1][3], uAl + laneA + koff + 16 * PITCH * 2);
            #pragma unroll
            for (int mi = 0; mi < 2; mi++)
                #pragma unroll
                for (int g = 0; g < 4; g++) {
                    MMA16816(acc[mi][g * 2 + 0], a[mi], b[g][0], b[g][1]);
                    MMA16816(acc[mi][g * 2 + 1], a[mi], b[g][2], b[g][3]);
                }

            // pass 3: Ahi * Blo
            LDSM4(a[0][0], a[0][1], a[0][2], a[0][3], uAh + laneA + koff);
            LDSM4(a[1][0], a[1][1], a[1][2], a[1][3], uAh + laneA + koff + 16 * PITCH * 2);
            #pragma unroll
            for (int g = 0; g < 4; g++)
                LDSM4(b[g][0], b[g][1], b[g][2], b[g][3],
                      uBl + laneB + koff + g * 16 * PITCH * 2);
            #pragma unroll
            for (int mi = 0; mi < 2; mi++)
                #pragma unroll
                for (int g = 0; g < 4; g++) {
                    MMA16816(acc[mi][g * 2 + 0], a[mi], b[g][0], b[g][1]);
                    MMA16816(acc[mi][g * 2 + 1], a[mi], b[g][2], b[g][3]);
                }
        }
        __syncthreads();
    }

    // ---- epilogue: bias + store ----
    int cb = (l & 3) * 2;
    int rbase = m0 + wm + (l >> 2);
    #pragma unroll
    for (int mi = 0; mi < 2; mi++) {
        #pragma unroll
        for (int nj = 0; nj < 8; nj++) {
            int col = wn + nj * 8 + cb;
            float b0 = sBias[col], b1 = sBias[col + 1];
            int r0 = rbase + mi * 16;
            if (r0 < NN) {
                float2 v = make_float2(acc[mi][nj][0] + b0, acc[mi][nj][1] + b1);
                *(float2*)(out + (size_t)r0 * NOUT + n0 + col) = v;
            }
            int r1 = r0 + 8;
            if (r1 < NN) {
                float2 v = make_float2(acc[mi][nj][2] + b0, acc[mi][nj][3] + b1);
                *(float2*)(out + (size_t)r1 * NOUT + n0 + col) = v;
            }
        }
    }
}

extern "C" void kernel_launch(void* const* d_in, const int* in_sizes, int n_in,
                              void* d_out, int out_size) {
    const float* features = (const float*)d_in[0];
    const int*   src      = (const int*)d_in[1];
    const int*   dst      = (const int*)d_in[2];
    const float* W        = (const float*)d_in[3];
    const float* bias     = (const float*)d_in[4];
    float*       out      = (float*)d_out;

    k_zero_cnt<<<(NN + 255) / 256, 256>>>();
    k_fill<<<(NE + 255) / 256, 256>>>(src, dst);
    k_prepW<<<(NOUT * KIN + 255) / 256, 256>>>(W);
    k_agg<<<NN / 8, 256>>>(features);
    k_gemm_mma<<<(NPAD / MT) * (NOUT / NTB), 256>>>(bias, out);
}